// round 4
// baseline (speedup 1.0000x reference)
#include <cuda_runtime.h>

#define NH 8
#define TT 256
#define DHD 64
#define DD 512
#define NSPLIT 8

// ---------------- scratch (static __device__, allocation-free) ----------------
__device__ float g_heads[5][NH][TT][DHD];          // k1,k2,q,v1,v2  (2.5 MB)
__device__ float g_Wq[NH][TT][DHD * DHD];          // [h][q][k*64+j]  (33.5 MB)
__device__ float g_S[NH][TT][TT][TT];              // [h][q][p][t]    (537 MB)
__device__ float g_T1[NH][TT][TT][DHD];            // [h][q][p][c]    (134 MB)
__device__ float g_R[NH][TT][DHD * DHD];           // [h][q][a*64+c]  (33.5 MB)
__device__ float g_rowsum[NH][TT];
__device__ float g_zp[NSPLIT][NH][4][64][64];      // z split-K partials (4 MB)
__device__ float g_z[TT][DD];                      // attention output (512 KB)

// ------- 64x64 tile GEMM, 256 thr, 4x4/thread; A stored TRANSPOSED in smem ----
// As[k][m], Bs[k][n]; inner loop: 2x LDS.128 + 16 FFMA per k-step.

// A row-major [m][k] -> As[k][m] (scatter store)
__device__ __forceinline__ void load_AT(const float* __restrict__ A, int lda,
                                        float As[64][68], int tid) {
#pragma unroll
    for (int i = 0; i < 4; i++) {
        int id = tid + i * 256;
        int r = id >> 4, c = (id & 15) << 2;   // r = m, c = k base
        float4 v = *reinterpret_cast<const float4*>(A + (long)r * lda + c);
        As[c][r] = v.x; As[c + 1][r] = v.y; As[c + 2][r] = v.z; As[c + 3][r] = v.w;
    }
}
// X row-major [k][m] -> As[k][m] (direct vector copy)
__device__ __forceinline__ void load_Adir(const float* __restrict__ X, int ldx,
                                          float As[64][68], int tid) {
#pragma unroll
    for (int i = 0; i < 4; i++) {
        int id = tid + i * 256;
        int r = id >> 4, c = (id & 15) << 2;
        float4 v = *reinterpret_cast<const float4*>(X + (long)r * ldx + c);
        *reinterpret_cast<float4*>(&As[r][c]) = v;
    }
}
// B row-major [k][n] -> Bs[k][n]
__device__ __forceinline__ void load_B64(const float* __restrict__ B, int ldb,
                                         float Bs[64][68], int tid) {
#pragma unroll
    for (int i = 0; i < 4; i++) {
        int id = tid + i * 256;
        int r = id >> 4, c = (id & 15) << 2;
        float4 v = *reinterpret_cast<const float4*>(B + (long)r * ldb + c);
        *reinterpret_cast<float4*>(&Bs[r][c]) = v;
    }
}
// B given as [n][k] row-major -> Bs[k][n]
__device__ __forceinline__ void load_Bt64(const float* __restrict__ Bt, int ldbt,
                                          float Bs[64][68], int tid) {
#pragma unroll
    for (int i = 0; i < 4; i++) {
        int id = tid + i * 256;
        int n = id >> 4, c = (id & 15) << 2;
        float4 v = *reinterpret_cast<const float4*>(Bt + (long)n * ldbt + c);
        Bs[c][n] = v.x; Bs[c + 1][n] = v.y; Bs[c + 2][n] = v.z; Bs[c + 3][n] = v.w;
    }
}
__device__ __forceinline__ void mma64(const float As[64][68], const float Bs[64][68],
                                      float acc[4][4], int tm, int tn) {
#pragma unroll
    for (int k = 0; k < 64; k++) {
        float4 a = *reinterpret_cast<const float4*>(&As[k][tm * 4]);
        float4 b = *reinterpret_cast<const float4*>(&Bs[k][tn * 4]);
        acc[0][0] += a.x * b.x; acc[0][1] += a.x * b.y; acc[0][2] += a.x * b.z; acc[0][3] += a.x * b.w;
        acc[1][0] += a.y * b.x; acc[1][1] += a.y * b.y; acc[1][2] += a.y * b.z; acc[1][3] += a.y * b.w;
        acc[2][0] += a.z * b.x; acc[2][1] += a.z * b.y; acc[2][2] += a.z * b.z; acc[2][3] += a.z * b.w;
        acc[3][0] += a.w * b.x; acc[3][1] += a.w * b.y; acc[3][2] += a.w * b.z; acc[3][3] += a.w * b.w;
    }
}

// ---------------- K0: proj = x @ W_kkqvv + b, scatter head-major --------------
__global__ __launch_bounds__(256) void proj_kernel(const float* __restrict__ x,
                                                   const float* __restrict__ W,
                                                   const float* __restrict__ bias) {
    __shared__ float As[64][68];
    __shared__ float Bs[64][68];
    int tid = threadIdx.x, tm = tid >> 4, tn = tid & 15;
    int n0 = blockIdx.x * 64, m0 = blockIdx.y * 64;
    float acc[4][4] = {};
    for (int k0 = 0; k0 < DD; k0 += 64) {
        load_AT(x + (long)m0 * DD + k0, DD, As, tid);
        load_B64(W + (long)k0 * (5 * DD) + n0, 5 * DD, Bs, tid);
        __syncthreads();
        mma64(As, Bs, acc, tm, tn);
        __syncthreads();
    }
#pragma unroll
    for (int r = 0; r < 4; r++)
#pragma unroll
        for (int c = 0; c < 4; c++) {
            int row = m0 + tm * 4 + r;
            int col = n0 + tn * 4 + c;
            float v = acc[r][c] + bias[col];
            int part = col >> 9;           // k1,k2,q,v1,v2
            int rem = col & 511;
            g_heads[part][rem >> 6][row][rem & 63] = v;
        }
}

// ---------------- K1: Wq[h][q][k,j] = sum_i W_Kq[h][k,j][i] * q[h][q][i] ------
__global__ __launch_bounds__(256) void wq_kernel(const float* __restrict__ WKq) {
    __shared__ float As[64][68];
    __shared__ float Bs[64][68];
    int tid = threadIdx.x, tm = tid >> 4, tn = tid & 15;
    int kj0 = blockIdx.x * 64, q0 = blockIdx.y * 64, h = blockIdx.z;
    const float* A = &g_heads[2][h][q0][0];                       // q rows [q][i]
    const float* Bt = WKq + ((long)h * 4096 + kj0) * 64;          // [kj][i] rows
    float acc[4][4] = {};
    load_AT(A, 64, As, tid);
    load_Bt64(Bt, 64, Bs, tid);
    __syncthreads();
    mma64(As, Bs, acc, tm, tn);
#pragma unroll
    for (int r = 0; r < 4; r++)
#pragma unroll
        for (int c = 0; c < 4; c++)
            g_Wq[h][q0 + tm * 4 + r][kj0 + tn * 4 + c] = acc[r][c];
}

// ---- K2 (fused): Aq tile in smem (transposed), then S over all t-tiles -------
// Aq[p][j] = sum_k k1[p][k] * Wq[q][k][j];  S[p][t] = (1/64) sum_j Aq[p][j] k2[t][j]
__global__ __launch_bounds__(256) void aqattn_kernel() {
    int pt = blockIdx.x, q = blockIdx.y, h = blockIdx.z;
    int qt = q >> 6;
    if (pt > qt) return;
    __shared__ float As[64][68];
    __shared__ float Bs[64][68];
    __shared__ float AqS[64][68];    // [j][p] (contraction-major for phase 2)
    int tid = threadIdx.x, tm = tid >> 4, tn = tid & 15;
    int p0 = pt << 6;

    load_AT(&g_heads[0][h][p0][0], 64, As, tid);    // k1 [p][k] -> As[k][p]
    load_B64(&g_Wq[h][q][0], 64, Bs, tid);          // Wq [k][j]
    __syncthreads();
    float accA[4][4] = {};
    mma64(As, Bs, accA, tm, tn);                    // accA: p=tm*4+r, j=tn*4+c
    __syncthreads();
#pragma unroll
    for (int r = 0; r < 4; r++)
#pragma unroll
        for (int c = 0; c < 4; c++)
            AqS[tn * 4 + c][tm * 4 + r] = accA[r][c];   // AqS[j][p]
    __syncthreads();

    float* C = &g_S[h][q][0][0];
    for (int tt = 0; tt <= qt; tt++) {
        load_Bt64(&g_heads[1][h][tt * 64][0], 64, Bs, tid);  // k2 [t][j] -> Bs[j][t]
        __syncthreads();
        float acc[4][4] = {};
        mma64(AqS, Bs, acc, tm, tn);                // p=tm*4+r, t=tn*4+c
#pragma unroll
        for (int r = 0; r < 4; r++)
#pragma unroll
            for (int c = 0; c < 4; c++) {
                int p = p0 + tm * 4 + r;
                int t = tt * 64 + tn * 4 + c;
                float v = (p > q || t > q) ? -1e30f : acc[r][c] * (1.0f / 64.0f);
                C[(long)p * TT + t] = v;
            }
        __syncthreads();
    }
}

// ---------------- K3: softmax over valid [P x P] region (unnormalized) --------
__global__ __launch_bounds__(256) void softmax_kernel() {
    int q = blockIdx.x, h = blockIdx.y;
    int tid = threadIdx.x;
    int P = ((q >> 6) + 1) << 6;
    int P4 = P >> 2;
    int total4 = P * P4;
    float* row = &g_S[h][q][0][0];
    __shared__ float red[256];

    float m = -3.0e38f;
    for (int id = tid; id < total4; id += 256) {
        int p = id / P4, t4 = id - p * P4;
        float4 v = *reinterpret_cast<const float4*>(row + (long)p * TT + t4 * 4);
        m = fmaxf(m, fmaxf(fmaxf(v.x, v.y), fmaxf(v.z, v.w)));
    }
    red[tid] = m;
    __syncthreads();
    for (int off = 128; off > 0; off >>= 1) {
        if (tid < off) red[tid] = fmaxf(red[tid], red[tid + off]);
        __syncthreads();
    }
    float M = red[0];
    __syncthreads();

    float s = 0.0f;
    for (int id = tid; id < total4; id += 256) {
        int p = id / P4, t4 = id - p * P4;
        float4* ptr = reinterpret_cast<float4*>(row + (long)p * TT + t4 * 4);
        float4 v = *ptr;
        float4 e;
        e.x = __expf(v.x - M); e.y = __expf(v.y - M);
        e.z = __expf(v.z - M); e.w = __expf(v.w - M);
        s += (e.x + e.y) + (e.z + e.w);
        *ptr = e;
    }
    red[tid] = s;
    __syncthreads();
    for (int off = 128; off > 0; off >>= 1) {
        if (tid < off) red[tid] += red[tid + off];
        __syncthreads();
    }
    if (tid == 0) g_rowsum[h][q] = red[0];
}

// ---------------- K4: T1[h][q][p][c] = sum_t P[h][q][p][t] * v2[h][t][c] ------
__global__ __launch_bounds__(256) void t1_kernel() {
    int pt = blockIdx.x, q = blockIdx.y, h = blockIdx.z;
    int qt = q >> 6;
    if (pt > qt) return;
    __shared__ float As[64][68];
    __shared__ float Bs[64][68];
    int tid = threadIdx.x, tm = tid >> 4, tn = tid & 15;
    int p0 = pt << 6;
    const float* Pm = &g_S[h][q][p0][0];        // [64 p][t], ld 256
    const float* v2 = &g_heads[4][h][0][0];     // [256 t][64 c]
    float acc[4][4] = {};
    for (int ks = 0; ks <= qt; ks++) {
        load_AT(Pm + ks * 64, TT, As, tid);     // P[p][t] -> As[t][p]
        load_B64(v2 + ks * 64 * 64, 64, Bs, tid);
        __syncthreads();
        mma64(As, Bs, acc, tm, tn);
        __syncthreads();
    }
    float* C = &g_T1[h][q][p0][0];
#pragma unroll
    for (int r = 0; r < 4; r++)
#pragma unroll
        for (int c = 0; c < 4; c++)
            C[(tm * 4 + r) * 64 + tn * 4 + c] = acc[r][c];
}

// ---------------- K5: R[h][q][a][c] = sum_p v1[h][p][a] * T1[h][q][p][c] ------
__global__ __launch_bounds__(256) void r_kernel() {
    int q = blockIdx.x, h = blockIdx.y;
    int qt = q >> 6;
    __shared__ float As[64][68];
    __shared__ float Bs[64][68];
    int tid = threadIdx.x, tm = tid >> 4, tn = tid & 15;
    const float* v1 = &g_heads[3][h][0][0];     // [256 p][64 a] (already contraction-major)
    const float* T1 = &g_T1[h][q][0][0];        // [256 p][64 c]
    float acc[4][4] = {};
    for (int ks = 0; ks <= qt; ks++) {
        load_Adir(v1 + ks * 64 * 64, 64, As, tid);   // As[p][a], direct copy
        load_B64(T1 + ks * 64 * 64, 64, Bs, tid);    // Bs[p][c]
        __syncthreads();
        mma64(As, Bs, acc, tm, tn);                  // a=tm*4+r, c=tn*4+c
        __syncthreads();
    }
    float* C = &g_R[h][q][0];
#pragma unroll
    for (int r = 0; r < 4; r++)
#pragma unroll
        for (int c = 0; c < 4; c++)
            C[(tm * 4 + r) * 64 + tn * 4 + c] = acc[r][c];
}

// ---------------- K6: z_part = R @ W_Vq (split-K over ac) ---------------------
__global__ __launch_bounds__(256) void zp_kernel(const float* __restrict__ WVq) {
    __shared__ float As[64][68];
    __shared__ float Bs[64][68];
    int tid = threadIdx.x, tm = tid >> 4, tn = tid & 15;
    int sp = blockIdx.x, qt = blockIdx.y, h = blockIdx.z;
    int q0 = qt << 6;
    int ac0 = sp * (4096 / NSPLIT);
    const float* A = &g_R[h][q0][0];                    // [64 q][4096 ac]
    const float* B = WVq + ((long)h * 4096 + ac0) * 64; // [ac][64 e]
    float acc[4][4] = {};
    for (int ks = 0; ks < 4096 / NSPLIT / 64; ks++) {
        load_AT(A + ac0 + ks * 64, 4096, As, tid);
        load_B64(B + (long)ks * 64 * 64, 64, Bs, tid);
        __syncthreads();
        mma64(As, Bs, acc, tm, tn);
        __syncthreads();
    }
    float* C = &g_zp[sp][h][qt][0][0];
#pragma unroll
    for (int r = 0; r < 4; r++)
#pragma unroll
        for (int c = 0; c < 4; c++)
            C[(tm * 4 + r) * 64 + tn * 4 + c] = acc[r][c];
}

// ---------------- K7: reduce split-K, divide by rowsum ------------------------
__global__ __launch_bounds__(256) void zred_kernel() {
    int idx = blockIdx.x * 256 + threadIdx.x;  // 256*512
    int q = idx >> 9, col = idx & 511;
    int h = col >> 6, e = col & 63;
    int qt = q >> 6, ql = q & 63;
    float s = 0.0f;
#pragma unroll
    for (int sp = 0; sp < NSPLIT; sp++) s += g_zp[sp][h][qt][ql][e];
    g_z[q][col] = s / g_rowsum[h][q];
}

// ---------------- K8: out = z @ W_out + b_out ---------------------------------
__global__ __launch_bounds__(256) void out_kernel(const float* __restrict__ Wout,
                                                  const float* __restrict__ bout,
                                                  float* __restrict__ out) {
    __shared__ float As[64][68];
    __shared__ float Bs[64][68];
    int tid = threadIdx.x, tm = tid >> 4, tn = tid & 15;
    int n0 = blockIdx.x * 64, m0 = blockIdx.y * 64;
    float acc[4][4] = {};
    for (int k0 = 0; k0 < DD; k0 += 64) {
        load_AT(&g_z[m0][k0], DD, As, tid);
        load_B64(Wout + (long)k0 * DD + n0, DD, Bs, tid);
        __syncthreads();
        mma64(As, Bs, acc, tm, tn);
        __syncthreads();
    }
#pragma unroll
    for (int r = 0; r < 4; r++)
#pragma unroll
        for (int c = 0; c < 4; c++) {
            int row = m0 + tm * 4 + r;
            int col = n0 + tn * 4 + c;
            out[(long)row * DD + col] = acc[r][c] + bout[col];
        }
}

// ---------------- launch ------------------------------------------------------
extern "C" void kernel_launch(void* const* d_in, const int* in_sizes, int n_in,
                              void* d_out, int out_size) {
    const float* x    = (const float*)d_in[0];
    const float* Wkk  = (const float*)d_in[1];
    const float* bkk  = (const float*)d_in[2];
    const float* WKq  = (const float*)d_in[3];
    const float* WVq  = (const float*)d_in[4];
    const float* Wout = (const float*)d_in[5];
    const float* bout = (const float*)d_in[6];
    float* out = (float*)d_out;

    proj_kernel<<<dim3(40, 4), 256>>>(x, Wkk, bkk);
    wq_kernel<<<dim3(64, 4, NH), 256>>>(WKq);
    aqattn_kernel<<<dim3(4, TT, NH), 256>>>();
    softmax_kernel<<<dim3(TT, NH), 256>>>();
    t1_kernel<<<dim3(4, TT, NH), 256>>>();
    r_kernel<<<dim3(TT, NH), 256>>>();
    zp_kernel<<<dim3(NSPLIT, 4, NH), 256>>>(WVq);
    zred_kernel<<<512, 256>>>();
    out_kernel<<<dim3(8, 4), 256>>>(Wout, bout, out);
}

// round 8
// speedup vs baseline: 1.7089x; 1.7089x over previous
#include <cuda_runtime.h>
#include <cstdint>

#define NH 8
#define TT 256
#define DHD 64
#define DD 512
#define NSPLIT 8

// ---------------- scratch (static __device__, allocation-free) ----------------
__device__ float g_heads[5][NH][TT][DHD];          // k1,k2,q,v1,v2  (2.5 MB)
__device__ float g_Wq[NH][TT][DHD * DHD];          // [h][q][k*64+j]  (33.5 MB)
__device__ float g_S[NH][TT][TT][TT];              // [h][q][p][t]    (537 MB)
__device__ float g_T1[NH][TT][TT][DHD];            // [h][q][p][c]    (134 MB)
__device__ float g_R[NH][TT][DHD * DHD];           // [h][q][a*64+c]  (33.5 MB)
__device__ float g_pmax[NH][TT][4];                // per-stripe max of S
__device__ float g_psum[NH][TT][4];                // per-stripe sum of exp
__device__ float g_zp[NSPLIT][NH][4][64][64];      // z split-K partials (4 MB)
__device__ float g_z[TT][DD];                      // attention output (512 KB)

// ============================ TF32 MMA machinery ==============================
__device__ __forceinline__ float to_tf32(float x) {
    uint32_t u; asm("cvt.rna.tf32.f32 %0, %1;" : "=r"(u) : "f"(x));
    return __uint_as_float(u);
}
__device__ __forceinline__ void mma8(float* c, float a0, float a1, float a2, float a3,
                                     float b0, float b1) {
    asm volatile(
        "mma.sync.aligned.m16n8k8.row.col.f32.tf32.tf32.f32 "
        "{%0,%1,%2,%3},{%4,%5,%6,%7},{%8,%9},{%0,%1,%2,%3};"
        : "+f"(c[0]), "+f"(c[1]), "+f"(c[2]), "+f"(c[3])
        : "r"(__float_as_uint(a0)), "r"(__float_as_uint(a1)),
          "r"(__float_as_uint(a2)), "r"(__float_as_uint(a3)),
          "r"(__float_as_uint(b0)), "r"(__float_as_uint(b1)));
}
// Warp computes a 16x32 chunk of a 64x64 tile. As[m][k] pad 68, Bs[k][n] pad 72.
__device__ __forceinline__ void wtile(const float (*As)[68], const float (*Bs)[72],
                                      float acc[4][4], int m0, int n0, int gid, int tig) {
#pragma unroll
    for (int kc = 0; kc < 64; kc += 8) {
        float a0 = As[m0 + gid][kc + tig],     a1 = As[m0 + gid + 8][kc + tig];
        float a2 = As[m0 + gid][kc + tig + 4], a3 = As[m0 + gid + 8][kc + tig + 4];
#pragma unroll
        for (int nt = 0; nt < 4; nt++) {
            int n = n0 + nt * 8;
            mma8(acc[nt], a0, a1, a2, a3, Bs[kc + tig][n + gid], Bs[kc + tig + 4][n + gid]);
        }
    }
}
// 3xTF32 fused: acc += Ah*Bh + Al*Bh + Ah*Bl
__device__ __forceinline__ void wtile3(const float (*Ah)[68], const float (*Al)[68],
                                       const float (*Bh)[72], const float (*Bl)[72],
                                       float acc[4][4], int m0, int n0, int gid, int tig) {
#pragma unroll
    for (int kc = 0; kc < 64; kc += 8) {
        float ah0 = Ah[m0 + gid][kc + tig],     ah1 = Ah[m0 + gid + 8][kc + tig];
        float ah2 = Ah[m0 + gid][kc + tig + 4], ah3 = Ah[m0 + gid + 8][kc + tig + 4];
        float al0 = Al[m0 + gid][kc + tig],     al1 = Al[m0 + gid + 8][kc + tig];
        float al2 = Al[m0 + gid][kc + tig + 4], al3 = Al[m0 + gid + 8][kc + tig + 4];
#pragma unroll
        for (int nt = 0; nt < 4; nt++) {
            int n = n0 + nt * 8;
            float bh0 = Bh[kc + tig][n + gid], bh1 = Bh[kc + tig + 4][n + gid];
            float bl0 = Bl[kc + tig][n + gid], bl1 = Bl[kc + tig + 4][n + gid];
            mma8(acc[nt], ah0, ah1, ah2, ah3, bh0, bh1);
            mma8(acc[nt], al0, al1, al2, al3, bh0, bh1);
            mma8(acc[nt], ah0, ah1, ah2, ah3, bl0, bl1);
        }
    }
}
// gmem [m][k] -> As[m][k] (tf32)
__device__ __forceinline__ void ldA(const float* __restrict__ src, int lda,
                                    float (*As)[68], int tid) {
#pragma unroll
    for (int i = 0; i < 4; i++) {
        int id = tid + i * 256, r = id >> 4, c = (id & 15) << 2;
        float4 v = *reinterpret_cast<const float4*>(src + (long)r * lda + c);
        float4 w = {to_tf32(v.x), to_tf32(v.y), to_tf32(v.z), to_tf32(v.w)};
        *reinterpret_cast<float4*>(&As[r][c]) = w;
    }
}
// gmem [k][n] -> Bs[k][n] (tf32)
__device__ __forceinline__ void ldB(const float* __restrict__ src, int ldb,
                                    float (*Bs)[72], int tid) {
#pragma unroll
    for (int i = 0; i < 4; i++) {
        int id = tid + i * 256, r = id >> 4, c = (id & 15) << 2;
        float4 v = *reinterpret_cast<const float4*>(src + (long)r * ldb + c);
        float4 w = {to_tf32(v.x), to_tf32(v.y), to_tf32(v.z), to_tf32(v.w)};
        *reinterpret_cast<float4*>(&Bs[r][c]) = w;
    }
}
// gmem [n][k] -> Bs[k][n] (tf32)
__device__ __forceinline__ void ldBt(const float* __restrict__ src, int ldbt,
                                     float (*Bs)[72], int tid) {
#pragma unroll
    for (int i = 0; i < 4; i++) {
        int id = tid + i * 256, n = id & 63, kb = (id >> 6) << 2;
        float4 v = *reinterpret_cast<const float4*>(src + (long)n * ldbt + kb);
        Bs[kb][n] = to_tf32(v.x); Bs[kb + 1][n] = to_tf32(v.y);
        Bs[kb + 2][n] = to_tf32(v.z); Bs[kb + 3][n] = to_tf32(v.w);
    }
}
// split loaders: hi = tf32(x), lo = tf32(x - hi)
__device__ __forceinline__ void split1(float x, float& h, float& l) {
    h = to_tf32(x); l = to_tf32(x - h);
}
__device__ __forceinline__ void ldA_split(const float* __restrict__ src, int lda,
                                          float (*Ah)[68], float (*Al)[68], int tid) {
#pragma unroll
    for (int i = 0; i < 4; i++) {
        int id = tid + i * 256, r = id >> 4, c = (id & 15) << 2;
        float4 v = *reinterpret_cast<const float4*>(src + (long)r * lda + c);
        float4 h, l;
        split1(v.x, h.x, l.x); split1(v.y, h.y, l.y);
        split1(v.z, h.z, l.z); split1(v.w, h.w, l.w);
        *reinterpret_cast<float4*>(&Ah[r][c]) = h;
        *reinterpret_cast<float4*>(&Al[r][c]) = l;
    }
}
// gmem [k][m] -> As[m][k] split (transposed scatter)
__device__ __forceinline__ void ldAt_split(const float* __restrict__ src, int ldx,
                                           float (*Ah)[68], float (*Al)[68], int tid) {
#pragma unroll
    for (int i = 0; i < 4; i++) {
        int id = tid + i * 256, k = id & 63, mb = (id >> 6) << 2;
        float4 v = *reinterpret_cast<const float4*>(src + (long)k * ldx + mb);
        float h, l;
        split1(v.x, h, l); Ah[mb][k] = h;     Al[mb][k] = l;
        split1(v.y, h, l); Ah[mb + 1][k] = h; Al[mb + 1][k] = l;
        split1(v.z, h, l); Ah[mb + 2][k] = h; Al[mb + 2][k] = l;
        split1(v.w, h, l); Ah[mb + 3][k] = h; Al[mb + 3][k] = l;
    }
}
__device__ __forceinline__ void ldB_split(const float* __restrict__ src, int ldb,
                                          float (*Bh)[72], float (*Bl)[72], int tid) {
#pragma unroll
    for (int i = 0; i < 4; i++) {
        int id = tid + i * 256, r = id >> 4, c = (id & 15) << 2;
        float4 v = *reinterpret_cast<const float4*>(src + (long)r * ldb + c);
        float4 h, l;
        split1(v.x, h.x, l.x); split1(v.y, h.y, l.y);
        split1(v.z, h.z, l.z); split1(v.w, h.w, l.w);
        *reinterpret_cast<float4*>(&Bh[r][c]) = h;
        *reinterpret_cast<float4*>(&Bl[r][c]) = l;
    }
}
__device__ __forceinline__ void store_tile(float* C, int ldc, const float acc[4][4],
                                           int m0, int n0, int gid, int tig) {
#pragma unroll
    for (int nt = 0; nt < 4; nt++) {
        int n = n0 + nt * 8 + 2 * tig;
        *reinterpret_cast<float2*>(C + (long)(m0 + gid) * ldc + n) =
            make_float2(acc[nt][0], acc[nt][1]);
        *reinterpret_cast<float2*>(C + (long)(m0 + gid + 8) * ldc + n) =
            make_float2(acc[nt][2], acc[nt][3]);
    }
}

// dynamic-smem layout for split kernels (71680 B)
#define OFF_AH 0
#define OFF_AL (64 * 68)
#define OFF_BH (2 * 64 * 68)
#define OFF_BL (2 * 64 * 68 + 64 * 72)
#define SPLIT_SMEM ((2 * 64 * 68 + 2 * 64 * 72) * 4)

// ===================== legacy FFMA 64x64 tile (proj/out only) =================
__device__ __forceinline__ void f_loadAT(const float* __restrict__ A, int lda,
                                         float As[64][68], int tid) {
#pragma unroll
    for (int i = 0; i < 4; i++) {
        int id = tid + i * 256, r = id >> 4, c = (id & 15) << 2;
        float4 v = *reinterpret_cast<const float4*>(A + (long)r * lda + c);
        As[c][r] = v.x; As[c + 1][r] = v.y; As[c + 2][r] = v.z; As[c + 3][r] = v.w;
    }
}
__device__ __forceinline__ void f_loadB(const float* __restrict__ B, int ldb,
                                        float Bs[64][68], int tid) {
#pragma unroll
    for (int i = 0; i < 4; i++) {
        int id = tid + i * 256, r = id >> 4, c = (id & 15) << 2;
        float4 v = *reinterpret_cast<const float4*>(B + (long)r * ldb + c);
        *reinterpret_cast<float4*>(&Bs[r][c]) = v;
    }
}
__device__ __forceinline__ void f_mma(const float As[64][68], const float Bs[64][68],
                                      float acc[4][4], int tm, int tn) {
#pragma unroll
    for (int k = 0; k < 64; k++) {
        float4 a = *reinterpret_cast<const float4*>(&As[k][tm * 4]);
        float4 b = *reinterpret_cast<const float4*>(&Bs[k][tn * 4]);
        acc[0][0] += a.x * b.x; acc[0][1] += a.x * b.y; acc[0][2] += a.x * b.z; acc[0][3] += a.x * b.w;
        acc[1][0] += a.y * b.x; acc[1][1] += a.y * b.y; acc[1][2] += a.y * b.z; acc[1][3] += a.y * b.w;
        acc[2][0] += a.z * b.x; acc[2][1] += a.z * b.y; acc[2][2] += a.z * b.z; acc[2][3] += a.z * b.w;
        acc[3][0] += a.w * b.x; acc[3][1] += a.w * b.y; acc[3][2] += a.w * b.z; acc[3][3] += a.w * b.w;
    }
}

// ---------------- K0: proj = x @ W_kkqvv + b (fp32 FFMA), scatter -------------
__global__ __launch_bounds__(256) void proj_kernel(const float* __restrict__ x,
                                                   const float* __restrict__ W,
                                                   const float* __restrict__ bias) {
    __shared__ float As[64][68];
    __shared__ float Bs[64][68];
    int tid = threadIdx.x, tm = tid >> 4, tn = tid & 15;
    int n0 = blockIdx.x * 64, m0 = blockIdx.y * 64;
    float acc[4][4] = {};
    for (int k0 = 0; k0 < DD; k0 += 64) {
        f_loadAT(x + (long)m0 * DD + k0, DD, As, tid);
        f_loadB(W + (long)k0 * (5 * DD) + n0, 5 * DD, Bs, tid);
        __syncthreads();
        f_mma(As, Bs, acc, tm, tn);
        __syncthreads();
    }
#pragma unroll
    for (int r = 0; r < 4; r++)
#pragma unroll
        for (int c = 0; c < 4; c++) {
            int row = m0 + tm * 4 + r;
            int col = n0 + tn * 4 + c;
            float v = acc[r][c] + bias[col];
            int part = col >> 9;
            int rem = col & 511;
            g_heads[part][rem >> 6][row][rem & 63] = v;
        }
}

// ---------------- K1: Wq = q @ W_Kq^T (tf32) ----------------------------------
__global__ __launch_bounds__(256) void wq_kernel(const float* __restrict__ WKq) {
    __shared__ float As[64][68];
    __shared__ float Bs[64][72];
    int tid = threadIdx.x, w = tid >> 5, lane = tid & 31;
    int gid = lane >> 2, tig = lane & 3;
    int m0 = (w & 3) * 16, n0 = (w >> 2) * 32;
    int kj0 = blockIdx.x * 64, q0 = blockIdx.y * 64, h = blockIdx.z;
    ldA(&g_heads[2][h][q0][0], 64, As, tid);                 // q [q][i]
    ldBt(WKq + ((long)h * 4096 + kj0) * 64, 64, Bs, tid);    // WKq [kj][i] -> [i][kj]
    __syncthreads();
    float acc[4][4] = {};
    wtile(As, Bs, acc, m0, n0, gid, tig);
    store_tile(&g_Wq[h][q0][kj0], 4096, acc, m0, n0, gid, tig);
}

// ---- K2 (fused, tf32): Aq in smem, S over t-tiles, per-stripe max ------------
__global__ __launch_bounds__(256) void aqattn_kernel() {
    int pt = blockIdx.x, q = blockIdx.y, h = blockIdx.z;
    int qt = q >> 6;
    if (pt > qt) return;
    __shared__ float As[64][68];
    __shared__ float Bs[64][72];
    __shared__ float red[256];
    int tid = threadIdx.x, w = tid >> 5, lane = tid & 31;
    int gid = lane >> 2, tig = lane & 3;
    int m0 = (w & 3) * 16, n0 = (w >> 2) * 32;
    int p0 = pt << 6;

    ldA(&g_heads[0][h][p0][0], 64, As, tid);    // k1 [p][k]
    ldB(&g_Wq[h][q][0], 64, Bs, tid);           // Wq [k][j]
    __syncthreads();
    float accA[4][4] = {};
    wtile(As, Bs, accA, m0, n0, gid, tig);
    __syncthreads();
    // As := Aq[p][j] (tf32)
#pragma unroll
    for (int nt = 0; nt < 4; nt++) {
        int n = n0 + nt * 8 + 2 * tig;
        As[m0 + gid][n]     = to_tf32(accA[nt][0]);
        As[m0 + gid][n + 1] = to_tf32(accA[nt][1]);
        As[m0 + gid + 8][n]     = to_tf32(accA[nt][2]);
        As[m0 + gid + 8][n + 1] = to_tf32(accA[nt][3]);
    }
    __syncthreads();

    float vmax = -3.0e38f;
    float* C = &g_S[h][q][0][0];
    for (int tt = 0; tt <= qt; tt++) {
        ldBt(&g_heads[1][h][tt * 64][0], 64, Bs, tid);   // k2 [t][j] -> [j][t]
        __syncthreads();
        float acc[4][4] = {};
        wtile(As, Bs, acc, m0, n0, gid, tig);
#pragma unroll
        for (int nt = 0; nt < 4; nt++) {
            int n = n0 + nt * 8 + 2 * tig;
            int t = tt * 64 + n;
            int plo = p0 + m0 + gid, phi = plo + 8;
            float v00 = (plo > q || t > q)     ? -1e30f : acc[nt][0] * (1.0f / 64.0f);
            float v01 = (plo > q || t + 1 > q) ? -1e30f : acc[nt][1] * (1.0f / 64.0f);
            float v10 = (phi > q || t > q)     ? -1e30f : acc[nt][2] * (1.0f / 64.0f);
            float v11 = (phi > q || t + 1 > q) ? -1e30f : acc[nt][3] * (1.0f / 64.0f);
            *reinterpret_cast<float2*>(C + (long)plo * TT + t) = make_float2(v00, v01);
            *reinterpret_cast<float2*>(C + (long)phi * TT + t) = make_float2(v10, v11);
            vmax = fmaxf(vmax, fmaxf(fmaxf(v00, v01), fmaxf(v10, v11)));
        }
        __syncthreads();
    }
    red[tid] = vmax;
    __syncthreads();
    for (int off = 128; off > 0; off >>= 1) {
        if (tid < off) red[tid] = fmaxf(red[tid], red[tid + off]);
        __syncthreads();
    }
    if (tid == 0) g_pmax[h][q][pt] = red[0];
}

// ---- K3 (fused softmax + PV step 1, 3xTF32): T1 = exp(S-M) @ v2 --------------
__global__ __launch_bounds__(256) void t1_kernel() {
    int pt = blockIdx.x, q = blockIdx.y, h = blockIdx.z;
    int qt = q >> 6;
    if (pt > qt) return;
    extern __shared__ float sm[];
    float (*Ah)[68] = reinterpret_cast<float (*)[68]>(sm + OFF_AH);
    float (*Al)[68] = reinterpret_cast<float (*)[68]>(sm + OFF_AL);
    float (*Bh)[72] = reinterpret_cast<float (*)[72]>(sm + OFF_BH);
    float (*Bl)[72] = reinterpret_cast<float (*)[72]>(sm + OFF_BL);
    __shared__ float red[256];
    int tid = threadIdx.x, w = tid >> 5, lane = tid & 31;
    int gid = lane >> 2, tig = lane & 3;
    int m0 = (w & 3) * 16, n0 = (w >> 2) * 32;
    int p0 = pt << 6;

    float M = g_pmax[h][q][0];
    for (int pp = 1; pp <= qt; pp++) M = fmaxf(M, g_pmax[h][q][pp]);

    const float* Pm = &g_S[h][q][p0][0];        // [64 p][t], ld TT
    float lsum = 0.0f;
    float acc[4][4] = {};
    for (int ks = 0; ks <= qt; ks++) {
#pragma unroll
        for (int i = 0; i < 4; i++) {
            int id = tid + i * 256, r = id >> 4, c = (id & 15) << 2;
            float4 v = *reinterpret_cast<const float4*>(Pm + (long)r * TT + ks * 64 + c);
            float4 e = {__expf(v.x - M), __expf(v.y - M), __expf(v.z - M), __expf(v.w - M)};
            lsum += (e.x + e.y) + (e.z + e.w);
            float4 hh, ll;
            split1(e.x, hh.x, ll.x); split1(e.y, hh.y, ll.y);
            split1(e.z, hh.z, ll.z); split1(e.w, hh.w, ll.w);
            *reinterpret_cast<float4*>(&Ah[r][c]) = hh;
            *reinterpret_cast<float4*>(&Al[r][c]) = ll;
        }
        ldB_split(&g_heads[4][h][ks * 64][0], 64, Bh, Bl, tid);    // v2 [t][c]
        __syncthreads();
        wtile3(Ah, Al, Bh, Bl, acc, m0, n0, gid, tig);
        __syncthreads();
    }
    store_tile(&g_T1[h][q][p0][0], 64, acc, m0, n0, gid, tig);
    red[tid] = lsum;
    __syncthreads();
    for (int off = 128; off > 0; off >>= 1) {
        if (tid < off) red[tid] += red[tid + off];
        __syncthreads();
    }
    if (tid == 0) g_psum[h][q][pt] = red[0];
}

// ---------------- K4 (3xTF32): R[a][c] = sum_p v1[p][a] * T1[p][c] ------------
__global__ __launch_bounds__(256) void r_kernel() {
    int q = blockIdx.x, h = blockIdx.y;
    int qt = q >> 6;
    extern __shared__ float sm[];
    float (*Ah)[68] = reinterpret_cast<float (*)[68]>(sm + OFF_AH);
    float (*Al)[68] = reinterpret_cast<float (*)[68]>(sm + OFF_AL);
    float (*Bh)[72] = reinterpret_cast<float (*)[72]>(sm + OFF_BH);
    float (*Bl)[72] = reinterpret_cast<float (*)[72]>(sm + OFF_BL);
    int tid = threadIdx.x, w = tid >> 5, lane = tid & 31;
    int gid = lane >> 2, tig = lane & 3;
    int m0 = (w & 3) * 16, n0 = (w >> 2) * 32;
    float acc[4][4] = {};
    for (int ks = 0; ks <= qt; ks++) {
        ldAt_split(&g_heads[3][h][ks * 64][0], 64, Ah, Al, tid);   // v1 [p][a] -> [a][p]
        ldB_split(&g_T1[h][q][ks * 64][0], 64, Bh, Bl, tid);       // T1 [p][c]
        __syncthreads();
        wtile3(Ah, Al, Bh, Bl, acc, m0, n0, gid, tig);
        __syncthreads();
    }
    store_tile(&g_R[h][q][0], 64, acc, m0, n0, gid, tig);
}

// ---------------- K5 (3xTF32): z_part = R @ W_Vq (split-K over ac) ------------
__global__ __launch_bounds__(256) void zp_kernel(const float* __restrict__ WVq) {
    extern __shared__ float sm[];
    float (*Ah)[68] = reinterpret_cast<float (*)[68]>(sm + OFF_AH);
    float (*Al)[68] = reinterpret_cast<float (*)[68]>(sm + OFF_AL);
    float (*Bh)[72] = reinterpret_cast<float (*)[72]>(sm + OFF_BH);
    float (*Bl)[72] = reinterpret_cast<float (*)[72]>(sm + OFF_BL);
    int tid = threadIdx.x, w = tid >> 5, lane = tid & 31;
    int gid = lane >> 2, tig = lane & 3;
    int m0 = (w & 3) * 16, n0 = (w >> 2) * 32;
    int sp = blockIdx.x, qt = blockIdx.y, h = blockIdx.z;
    int q0 = qt << 6;
    int ac0 = sp * (4096 / NSPLIT);
    float acc[4][4] = {};
    for (int ks = 0; ks < 4096 / NSPLIT / 64; ks++) {
        ldA_split(&g_R[h][q0][0] + ac0 + ks * 64, 4096, Ah, Al, tid);
        ldB_split(WVq + ((long)h * 4096 + ac0 + ks * 64) * 64, 64, Bh, Bl, tid);
        __syncthreads();
        wtile3(Ah, Al, Bh, Bl, acc, m0, n0, gid, tig);
        __syncthreads();
    }
    store_tile(&g_zp[sp][h][qt][0][0], 64, acc, m0, n0, gid, tig);
}

// ---------------- K6: reduce split-K, divide by rowsum ------------------------
__global__ __launch_bounds__(256) void zred_kernel() {
    int idx = blockIdx.x * 256 + threadIdx.x;  // 256*512
    int q = idx >> 9, col = idx & 511;
    int h = col >> 6;
    int qt = q >> 6, ql = q & 63;
    int e = col & 63;
    float s = 0.0f;
#pragma unroll
    for (int sp = 0; sp < NSPLIT; sp++) s += g_zp[sp][h][qt][ql][e];
    float rs = 0.0f;
    for (int pp = 0; pp <= qt; pp++) rs += g_psum[h][q][pp];
    g_z[q][col] = s / rs;
}

// ---------------- K7: out = z @ W_out + b_out (fp32 FFMA) ---------------------
__global__ __launch_bounds__(256) void out_kernel(const float* __restrict__ Wout,
                                                  const float* __restrict__ bout,
                                                  float* __restrict__ out) {
    __shared__ float As[64][68];
    __shared__ float Bs[64][68];
    int tid = threadIdx.x, tm = tid >> 4, tn = tid & 15;
    int n0 = blockIdx.x * 64, m0 = blockIdx.y * 64;
    float acc[4][4] = {};
    for (int k0 = 0; k0 < DD; k0 += 64) {
        f_loadAT(&g_z[m0][k0], DD, As, tid);
        f_loadB(Wout + (long)k0 * DD + n0, DD, Bs, tid);
        __syncthreads();
        f_mma(As, Bs, acc, tm, tn);
        __syncthreads();
    }
#pragma unroll
    for (int r = 0; r < 4; r++)
#pragma unroll
        for (int c = 0; c < 4; c++) {
            int row = m0 + tm * 4 + r;
            int col = n0 + tn * 4 + c;
            out[(long)row * DD + col] = acc[r][c] + bout[col];
        }
}

// ---------------- launch ------------------------------------------------------
extern "C" void kernel_launch(void* const* d_in, const int* in_sizes, int n_in,
                              void* d_out, int out_size) {
    const float* x    = (const float*)d_in[0];
    const float* Wkk  = (const float*)d_in[1];
    const float* bkk  = (const float*)d_in[2];
    const float* WKq  = (const float*)d_in[3];
    const float* WVq  = (const float*)d_in[4];
    const float* Wout = (const float*)d_in[5];
    const float* bout = (const float*)d_in[6];
    float* out = (float*)d_out;

    cudaFuncSetAttribute(t1_kernel, cudaFuncAttributeMaxDynamicSharedMemorySize, SPLIT_SMEM);
    cudaFuncSetAttribute(r_kernel,  cudaFuncAttributeMaxDynamicSharedMemorySize, SPLIT_SMEM);
    cudaFuncSetAttribute(zp_kernel, cudaFuncAttributeMaxDynamicSharedMemorySize, SPLIT_SMEM);

    proj_kernel<<<dim3(40, 4), 256>>>(x, Wkk, bkk);
    wq_kernel<<<dim3(64, 4, NH), 256>>>(WKq);
    aqattn_kernel<<<dim3(4, TT, NH), 256>>>();
    t1_kernel<<<dim3(4, TT, NH), 256, SPLIT_SMEM>>>();
    r_kernel<<<dim3(TT, NH), 256, SPLIT_SMEM>>>();
    zp_kernel<<<dim3(NSPLIT, 4, NH), 256, SPLIT_SMEM>>>(WVq);
    zred_kernel<<<512, 256>>>();
    out_kernel<<<dim3(8, 4), 256>>>(Wout, bout, out);
}